// round 6
// baseline (speedup 1.0000x reference)
#include <cuda_runtime.h>
#include <cuda_fp16.h>
#include <cstdint>

// ScorePredictor: score[e] = dot(x[src[e]], x[dst[e]])
// x: [N, 64] fp32, src/dst: [E] int32 or int64 (runtime-detected).
//
// R6: MLP=8 (4 edges / 8-lane group) + shuffle-distributed index loads
// (1 LDG per group instead of 8 broadcast LDGs) + launch_bounds(256,7) to
// recover occupancy lost in R5. fp16 node cache: 128B row = 1 L1 wavefront.

static constexpr int D_FEAT = 64;
static constexpr int MAX_NODES = 262144;
static constexpr int THREADS = 256;
static constexpr int EPG = 4;   // edges per 8-lane group

__device__ int g_idx_is_64 = 0;
__device__ __align__(16) __half g_xh[(size_t)MAX_NODES * D_FEAT];  // 32MB scratch

// --- fp32 -> fp16 conversion + dtype detection (thread 0). ---
__global__ __launch_bounds__(THREADS)
void convert_kernel(const float4* __restrict__ x4, int n4,
                    const unsigned int* __restrict__ idx_words)
{
    int i = blockIdx.x * THREADS + threadIdx.x;
    if (i == 0) {
        // int64 (LE, values < 2^31) => all odd 32-bit words zero.
        int is64 = 1;
        #pragma unroll
        for (int k = 0; k < 32; k++)
            if (idx_words[2 * k + 1] != 0u) { is64 = 0; break; }
        g_idx_is_64 = is64;
    }
    if (i >= n4) return;
    float4 v = x4[i];
    __half2 h0 = __floats2half2_rn(v.x, v.y);
    __half2 h1 = __floats2half2_rn(v.z, v.w);
    uint2 p;
    p.x = *reinterpret_cast<unsigned*>(&h0);
    p.y = *reinterpret_cast<unsigned*>(&h1);
    reinterpret_cast<uint2*>(g_xh)[i] = p;
}

__device__ __forceinline__ float dot16(const uint4& a, const uint4& b)
{
    float sum = 0.0f;
    const unsigned* ap = &a.x;
    const unsigned* bp = &b.x;
    #pragma unroll
    for (int j = 0; j < 4; j++) {
        __half2 ha = *reinterpret_cast<const __half2*>(&ap[j]);
        __half2 hb = *reinterpret_cast<const __half2*>(&bp[j]);
        float2 fa = __half22float2(ha);
        float2 fb = __half22float2(hb);
        sum = fmaf(fa.x, fb.x, sum);
        sum = fmaf(fa.y, fb.y, sum);
    }
    return sum;
}

// 8-lane group handles 4 edges. Lanes 0-3 load the 4 src indices, lanes 4-7
// the 4 dst indices; shfl distributes. All lanes always participate
// (clamped) so the full-warp shuffles are safe; stores are guarded.
__global__ __launch_bounds__(THREADS, 7)
void edge_dot_kernel(const void* __restrict__ src_raw,
                     const void* __restrict__ dst_raw,
                     float* __restrict__ out,
                     int n_edges)
{
    int tid   = blockIdx.x * THREADS + threadIdx.x;
    int g     = tid >> 3;
    int lane  = tid & 7;
    int ebase = g * EPG;
    int elast = n_edges - 1;

    // One index load per lane: lanes 0-3 -> src[ebase+lane],
    // lanes 4-7 -> dst[ebase+(lane-4)].
    int esub = ebase + (lane & 3);
    esub = esub < elast ? esub : elast;
    unsigned myidx;
    if (g_idx_is_64) {
        const unsigned long long* p = (lane < 4)
            ? (const unsigned long long*)src_raw
            : (const unsigned long long*)dst_raw;
        myidx = (unsigned)p[esub];
    } else {
        const unsigned* p = (lane < 4) ? (const unsigned*)src_raw
                                       : (const unsigned*)dst_raw;
        myidx = p[esub];
    }

    const uint4* xh4 = reinterpret_cast<const uint4*>(g_xh);

    // Distribute indices and issue all 8 gathers back-to-back (MLP=8).
    uint4 a[EPG], b[EPG];
    #pragma unroll
    for (int k = 0; k < EPG; k++) {
        unsigned s = __shfl_sync(0xFFFFFFFFu, myidx, k, 8);
        unsigned d = __shfl_sync(0xFFFFFFFFu, myidx, 4 + k, 8);
        a[k] = xh4[s * 8u + lane];
        b[k] = xh4[d * 8u + lane];
    }

    float sum[EPG];
    #pragma unroll
    for (int k = 0; k < EPG; k++)
        sum[k] = dot16(a[k], b[k]);

    #pragma unroll
    for (int off = 4; off >= 1; off >>= 1) {
        #pragma unroll
        for (int k = 0; k < EPG; k++)
            sum[k] += __shfl_down_sync(0xFFFFFFFFu, sum[k], off, 8);
    }

    if (lane == 0) {
        #pragma unroll
        for (int k = 0; k < EPG; k++) {
            int e = ebase + k;
            if (e < n_edges) out[e] = sum[k];
        }
    }
}

extern "C" void kernel_launch(void* const* d_in, const int* in_sizes, int n_in,
                              void* d_out, int out_size)
{
    // x = largest input; other two are index arrays (dot is symmetric).
    int xi = 0;
    for (int i = 1; i < n_in; i++)
        if (in_sizes[i] > in_sizes[xi]) xi = i;
    int i1 = -1, i2 = -1;
    for (int i = 0; i < n_in; i++) {
        if (i == xi) continue;
        if (i1 < 0) i1 = i; else i2 = i;
    }

    const float4* x4  = (const float4*)d_in[xi];
    const void*   src = d_in[i1];
    const void*   dst = d_in[i2];
    float*        out = (float*)d_out;

    int n_edges = in_sizes[i1];
    int n4      = in_sizes[xi] / 4;

    convert_kernel<<<(n4 + THREADS - 1) / THREADS, THREADS>>>(
        x4, n4, (const unsigned int*)src);

    long long groups = (n_edges + EPG - 1) / EPG;
    long long total_threads = groups * 8;
    int blocks = (int)((total_threads + THREADS - 1) / THREADS);
    edge_dot_kernel<<<blocks, THREADS>>>(src, dst, out, n_edges);
}

// round 7
// speedup vs baseline: 1.0664x; 1.0664x over previous
#include <cuda_runtime.h>
#include <cuda_fp16.h>
#include <cstdint>

// ScorePredictor: score[e] = dot(x[src[e]], x[dst[e]])
// x: [N, 64] fp32, src/dst: [E] int32 or int64 (runtime-detected).
//
// R7: 256B-align the fp16 node cache so each 128B row is exactly one L1
// line/wavefront (align(16) could straddle lines -> 2 wavefronts/gather).
// Butterfly reduce + coalesced 4-lane stores. MLP=8 via 4 edges per
// 8-lane group; fp32 accumulate.

static constexpr int D_FEAT = 64;
static constexpr int MAX_NODES = 262144;
static constexpr int THREADS = 256;
static constexpr int EPG = 4;   // edges per 8-lane group

__device__ int g_idx_is_64 = 0;
__device__ __align__(256) __half g_xh[(size_t)MAX_NODES * D_FEAT];  // 32MB scratch

// --- fp32 -> fp16 conversion + dtype detection (thread 0). ---
__global__ __launch_bounds__(THREADS)
void convert_kernel(const float4* __restrict__ x4, int n4,
                    const unsigned int* __restrict__ idx_words)
{
    int i = blockIdx.x * THREADS + threadIdx.x;
    if (i == 0) {
        // int64 (LE, values < 2^31) => all odd 32-bit words zero.
        int is64 = 1;
        #pragma unroll
        for (int k = 0; k < 32; k++)
            if (idx_words[2 * k + 1] != 0u) { is64 = 0; break; }
        g_idx_is_64 = is64;
    }
    if (i >= n4) return;
    float4 v = x4[i];
    __half2 h0 = __floats2half2_rn(v.x, v.y);
    __half2 h1 = __floats2half2_rn(v.z, v.w);
    uint2 p;
    p.x = *reinterpret_cast<unsigned*>(&h0);
    p.y = *reinterpret_cast<unsigned*>(&h1);
    reinterpret_cast<uint2*>(g_xh)[i] = p;
}

__device__ __forceinline__ float dot16(const uint4& a, const uint4& b)
{
    float sum = 0.0f;
    const unsigned* ap = &a.x;
    const unsigned* bp = &b.x;
    #pragma unroll
    for (int j = 0; j < 4; j++) {
        __half2 ha = *reinterpret_cast<const __half2*>(&ap[j]);
        __half2 hb = *reinterpret_cast<const __half2*>(&bp[j]);
        float2 fa = __half22float2(ha);
        float2 fb = __half22float2(hb);
        sum = fmaf(fa.x, fb.x, sum);
        sum = fmaf(fa.y, fb.y, sum);
    }
    return sum;
}

// 8-lane group handles 4 edges. Lanes 0-3 load src indices, lanes 4-7 dst.
// All lanes always participate (clamped) so full-warp shuffles are safe.
__global__ __launch_bounds__(THREADS, 7)
void edge_dot_kernel(const void* __restrict__ src_raw,
                     const void* __restrict__ dst_raw,
                     float* __restrict__ out,
                     int n_edges)
{
    int tid   = blockIdx.x * THREADS + threadIdx.x;
    int g     = tid >> 3;
    int lane  = tid & 7;
    int ebase = g * EPG;
    int elast = n_edges - 1;

    // One index load per lane.
    int esub = ebase + (lane & 3);
    esub = esub < elast ? esub : elast;
    unsigned myidx;
    if (g_idx_is_64) {
        const unsigned long long* p = (lane < 4)
            ? (const unsigned long long*)src_raw
            : (const unsigned long long*)dst_raw;
        myidx = (unsigned)p[esub];
    } else {
        const unsigned* p = (lane < 4) ? (const unsigned*)src_raw
                                       : (const unsigned*)dst_raw;
        myidx = p[esub];
    }

    const uint4* xh4 = reinterpret_cast<const uint4*>(g_xh);

    // Distribute indices and issue all 8 gathers back-to-back (MLP=8).
    uint4 a[EPG], b[EPG];
    #pragma unroll
    for (int k = 0; k < EPG; k++) {
        unsigned s = __shfl_sync(0xFFFFFFFFu, myidx, k, 8);
        unsigned d = __shfl_sync(0xFFFFFFFFu, myidx, 4 + k, 8);
        a[k] = xh4[s * 8u + lane];
        b[k] = xh4[d * 8u + lane];
    }

    float sum[EPG];
    #pragma unroll
    for (int k = 0; k < EPG; k++)
        sum[k] = dot16(a[k], b[k]);

    // Butterfly reduce: every lane ends with all 4 group totals.
    #pragma unroll
    for (int off = 4; off >= 1; off >>= 1) {
        #pragma unroll
        for (int k = 0; k < EPG; k++)
            sum[k] += __shfl_xor_sync(0xFFFFFFFFu, sum[k], off, 8);
    }

    // Coalesced store: lanes 0-3 of each group write 4 consecutive floats.
    float v = (lane & 2) ? ((lane & 1) ? sum[3] : sum[2])
                         : ((lane & 1) ? sum[1] : sum[0]);
    int eo = ebase + (lane & 3);
    if (lane < 4 && eo < n_edges) out[eo] = v;
}

extern "C" void kernel_launch(void* const* d_in, const int* in_sizes, int n_in,
                              void* d_out, int out_size)
{
    // x = largest input; other two are index arrays (dot is symmetric).
    int xi = 0;
    for (int i = 1; i < n_in; i++)
        if (in_sizes[i] > in_sizes[xi]) xi = i;
    int i1 = -1, i2 = -1;
    for (int i = 0; i < n_in; i++) {
        if (i == xi) continue;
        if (i1 < 0) i1 = i; else i2 = i;
    }

    const float4* x4  = (const float4*)d_in[xi];
    const void*   src = d_in[i1];
    const void*   dst = d_in[i2];
    float*        out = (float*)d_out;

    int n_edges = in_sizes[i1];
    int n4      = in_sizes[xi] / 4;

    convert_kernel<<<(n4 + THREADS - 1) / THREADS, THREADS>>>(
        x4, n4, (const unsigned int*)src);

    long long groups = (n_edges + EPG - 1) / EPG;
    long long total_threads = groups * 8;
    int blocks = (int)((total_threads + THREADS - 1) / THREADS);
    edge_dot_kernel<<<blocks, THREADS>>>(src, dst, out, n_edges);
}

// round 8
// speedup vs baseline: 1.1150x; 1.0456x over previous
#include <cuda_runtime.h>
#include <cuda_fp16.h>
#include <cstdint>

// ScorePredictor: score[e] = dot(x[src[e]], x[dst[e]])
// x: [N, 64] fp32, src/dst: [E] int32 or int64 (runtime-detected).
//
// R8: main kernel is at the LTS (L2) byte roof (~12.7TB/s delivered):
// 2.5M random 128B gathers from the L2-resident fp16 node cache, each
// exactly one line (256B-aligned scratch). This round shaves the convert
// pass: 8 floats/thread, single 16B store.

static constexpr int D_FEAT = 64;
static constexpr int MAX_NODES = 262144;
static constexpr int THREADS = 256;
static constexpr int EPG = 4;   // edges per 8-lane group

__device__ int g_idx_is_64 = 0;
__device__ __align__(256) __half g_xh[(size_t)MAX_NODES * D_FEAT];  // 32MB scratch

// --- fp32 -> fp16 conversion (8 floats/thread) + dtype detection. ---
__global__ __launch_bounds__(THREADS)
void convert_kernel(const float4* __restrict__ x4, int n8,
                    const unsigned int* __restrict__ idx_words)
{
    int i = blockIdx.x * THREADS + threadIdx.x;
    if (i == 0) {
        // int64 (LE, values < 2^31) => all odd 32-bit words zero.
        int is64 = 1;
        #pragma unroll
        for (int k = 0; k < 32; k++)
            if (idx_words[2 * k + 1] != 0u) { is64 = 0; break; }
        g_idx_is_64 = is64;
    }
    if (i >= n8) return;
    float4 v0 = x4[2 * i + 0];
    float4 v1 = x4[2 * i + 1];
    __half2 h0 = __floats2half2_rn(v0.x, v0.y);
    __half2 h1 = __floats2half2_rn(v0.z, v0.w);
    __half2 h2 = __floats2half2_rn(v1.x, v1.y);
    __half2 h3 = __floats2half2_rn(v1.z, v1.w);
    uint4 p;
    p.x = *reinterpret_cast<unsigned*>(&h0);
    p.y = *reinterpret_cast<unsigned*>(&h1);
    p.z = *reinterpret_cast<unsigned*>(&h2);
    p.w = *reinterpret_cast<unsigned*>(&h3);
    reinterpret_cast<uint4*>(g_xh)[i] = p;
}

__device__ __forceinline__ float dot16(const uint4& a, const uint4& b)
{
    float sum = 0.0f;
    const unsigned* ap = &a.x;
    const unsigned* bp = &b.x;
    #pragma unroll
    for (int j = 0; j < 4; j++) {
        __half2 ha = *reinterpret_cast<const __half2*>(&ap[j]);
        __half2 hb = *reinterpret_cast<const __half2*>(&bp[j]);
        float2 fa = __half22float2(ha);
        float2 fb = __half22float2(hb);
        sum = fmaf(fa.x, fb.x, sum);
        sum = fmaf(fa.y, fb.y, sum);
    }
    return sum;
}

// 8-lane group handles 4 edges. Lanes 0-3 load src indices, lanes 4-7 dst.
// All lanes always participate (clamped) so full-warp shuffles are safe.
__global__ __launch_bounds__(THREADS, 7)
void edge_dot_kernel(const void* __restrict__ src_raw,
                     const void* __restrict__ dst_raw,
                     float* __restrict__ out,
                     int n_edges)
{
    int tid   = blockIdx.x * THREADS + threadIdx.x;
    int g     = tid >> 3;
    int lane  = tid & 7;
    int ebase = g * EPG;
    int elast = n_edges - 1;
    int is64  = g_idx_is_64;   // uniform branch, hoisted

    // One index load per lane.
    int esub = ebase + (lane & 3);
    esub = esub < elast ? esub : elast;
    unsigned myidx;
    if (is64) {
        const unsigned long long* p = (lane < 4)
            ? (const unsigned long long*)src_raw
            : (const unsigned long long*)dst_raw;
        myidx = (unsigned)p[esub];
    } else {
        const unsigned* p = (lane < 4) ? (const unsigned*)src_raw
                                       : (const unsigned*)dst_raw;
        myidx = p[esub];
    }

    const uint4* xh4 = reinterpret_cast<const uint4*>(g_xh);

    // Distribute indices and issue all 8 gathers back-to-back (MLP=8).
    uint4 a[EPG], b[EPG];
    #pragma unroll
    for (int k = 0; k < EPG; k++) {
        unsigned s = __shfl_sync(0xFFFFFFFFu, myidx, k, 8);
        unsigned d = __shfl_sync(0xFFFFFFFFu, myidx, 4 + k, 8);
        a[k] = xh4[s * 8u + lane];
        b[k] = xh4[d * 8u + lane];
    }

    float sum[EPG];
    #pragma unroll
    for (int k = 0; k < EPG; k++)
        sum[k] = dot16(a[k], b[k]);

    // Butterfly reduce: every lane ends with all 4 group totals.
    #pragma unroll
    for (int off = 4; off >= 1; off >>= 1) {
        #pragma unroll
        for (int k = 0; k < EPG; k++)
            sum[k] += __shfl_xor_sync(0xFFFFFFFFu, sum[k], off, 8);
    }

    // Coalesced store: lanes 0-3 of each group write 4 consecutive floats.
    float v = (lane & 2) ? ((lane & 1) ? sum[3] : sum[2])
                         : ((lane & 1) ? sum[1] : sum[0]);
    int eo = ebase + (lane & 3);
    if (lane < 4 && eo < n_edges) out[eo] = v;
}

extern "C" void kernel_launch(void* const* d_in, const int* in_sizes, int n_in,
                              void* d_out, int out_size)
{
    // x = largest input; other two are index arrays (dot is symmetric).
    int xi = 0;
    for (int i = 1; i < n_in; i++)
        if (in_sizes[i] > in_sizes[xi]) xi = i;
    int i1 = -1, i2 = -1;
    for (int i = 0; i < n_in; i++) {
        if (i == xi) continue;
        if (i1 < 0) i1 = i; else i2 = i;
    }

    const float4* x4  = (const float4*)d_in[xi];
    const void*   src = d_in[i1];
    const void*   dst = d_in[i2];
    float*        out = (float*)d_out;

    int n_edges = in_sizes[i1];
    int n8      = in_sizes[xi] / 8;   // 8-float chunks of x

    convert_kernel<<<(n8 + THREADS - 1) / THREADS, THREADS>>>(
        x4, n8, (const unsigned int*)src);

    long long groups = (n_edges + EPG - 1) / EPG;
    long long total_threads = groups * 8;
    int blocks = (int)((total_threads + THREADS - 1) / THREADS);
    edge_dot_kernel<<<blocks, THREADS>>>(src, dst, out, n_edges);
}